// round 2
// baseline (speedup 1.0000x reference)
#include <cuda_runtime.h>
#include <cuda_bf16.h>
#include <cstdint>
#include <cstddef>

// ---------------------------------------------------------------------------
// Problem constants (fixed shapes)
// ---------------------------------------------------------------------------
static constexpr int MDIM = 8192;   // B*S
static constexpr int NDIM = 4096;   // D_OUT
static constexpr int KDIM = 4096;   // D_IN

static constexpr int MT = 128;      // M tile per CTA
static constexpr int NT = 256;      // N tile per CTA
static constexpr int KT = 64;       // K per pipeline stage
static constexpr int KB = KDIM / KT;          // 64 K-iterations
static constexpr int NSTAGE = 3;

static constexpr int A_TILE_BYTES = MT * KT * 2;          // 16384
static constexpr int W_TILE_BYTES = NT * KT * 2;          // 32768
static constexpr int STAGE_BYTES  = 2 * A_TILE_BYTES + W_TILE_BYTES; // 65536

static constexpr int SMEM_TOTAL = 2048 + NSTAGE * STAGE_BYTES;  // 198656

// ---------------------------------------------------------------------------
// Scratch (device globals — no allocation allowed in kernel_launch)
// Pre-swizzled (SW128), SMEM-ready tile blocks:
//   A: [mb(64)][kb(64)] blocks of 128 rows x 128B, 16KB each
//   W: [nbp(16)][kb(64)] blocks of 256 rows x 128B, 32KB each
// ---------------------------------------------------------------------------
__device__ __align__(1024) unsigned char g_Ahi[(size_t)MDIM * KDIM * 2];
__device__ __align__(1024) unsigned char g_Alo[(size_t)MDIM * KDIM * 2];
__device__ __align__(1024) unsigned char g_Wb [(size_t)NDIM * KDIM * 2];
__device__ float g_rowsum[MDIM];

// ---------------------------------------------------------------------------
// PTX helpers (base sm_90 PTX only — NOTHING 'a'-gated)
// ---------------------------------------------------------------------------
__device__ __forceinline__ uint32_t smem_u32(const void* p) {
    uint32_t a;
    asm("{ .reg .u64 t; cvta.to.shared.u64 t, %1; cvt.u32.u64 %0, t; }"
        : "=r"(a) : "l"(p));
    return a;
}

__device__ __forceinline__ uint32_t swz(uint32_t b) {
    return b ^ ((b >> 3) & 0x70);
}

__device__ __forceinline__ void mbar_init(uint32_t mbar, uint32_t cnt) {
    asm volatile("mbarrier.init.shared.b64 [%0], %1;" :: "r"(mbar), "r"(cnt) : "memory");
}

__device__ __forceinline__ void mbar_arrive(uint32_t mbar) {
    asm volatile("mbarrier.arrive.shared.b64 _, [%0];" :: "r"(mbar) : "memory");
}

__device__ __forceinline__ void mbar_expect_tx(uint32_t mbar, uint32_t bytes) {
    asm volatile("mbarrier.arrive.expect_tx.shared.b64 _, [%0], %1;"
                 :: "r"(mbar), "r"(bytes) : "memory");
}

__device__ __forceinline__ void bar_wait(uint32_t mbar, uint32_t parity) {
    uint32_t done;
    asm volatile("{\n .reg .pred p;\n"
                 " mbarrier.try_wait.parity.acquire.cta.shared::cta.b64 p, [%1], %2;\n"
                 " selp.b32 %0, 1, 0, p;\n}"
                 : "=r"(done) : "r"(mbar), "r"(parity) : "memory");
    while (!done) {
        asm volatile("{\n .reg .pred p;\n"
                     " mbarrier.try_wait.parity.acquire.cta.shared::cta.b64 p, [%1], %2, 0x989680;\n"
                     " selp.b32 %0, 1, 0, p;\n}"
                     : "=r"(done) : "r"(mbar), "r"(parity) : "memory");
    }
}

__device__ __forceinline__ void bulk_g2s(uint32_t dst_smem, const void* src,
                                         uint32_t bytes, uint32_t mbar) {
    asm volatile(
        "cp.async.bulk.shared::cluster.global.mbarrier::complete_tx::bytes "
        "[%0], [%1], %2, [%3];"
        :: "r"(dst_smem), "l"(src), "r"(bytes), "r"(mbar) : "memory");
}

__device__ __forceinline__ void ldsm_x4(uint32_t& r0, uint32_t& r1,
                                        uint32_t& r2, uint32_t& r3, uint32_t addr) {
    asm volatile("ldmatrix.sync.aligned.m8n8.x4.shared.b16 {%0,%1,%2,%3}, [%4];"
                 : "=r"(r0), "=r"(r1), "=r"(r2), "=r"(r3) : "r"(addr));
}

__device__ __forceinline__ void mma_bf16(float* c, uint32_t a0, uint32_t a1,
                                         uint32_t a2, uint32_t a3,
                                         uint32_t b0, uint32_t b1) {
    asm volatile("mma.sync.aligned.m16n8k16.row.col.f32.bf16.bf16.f32 "
                 "{%0,%1,%2,%3}, {%4,%5,%6,%7}, {%8,%9}, {%0,%1,%2,%3};"
                 : "+f"(c[0]), "+f"(c[1]), "+f"(c[2]), "+f"(c[3])
                 : "r"(a0), "r"(a1), "r"(a2), "r"(a3), "r"(b0), "r"(b1));
}

__device__ __forceinline__ uint32_t pack_bf16f(float lo, float hi) {
    __nv_bfloat162 t = __floats2bfloat162_rn(lo, hi);
    return *reinterpret_cast<uint32_t*>(&t);
}

__device__ __forceinline__ uint32_t pack_bf16(__nv_bfloat16 lo, __nv_bfloat16 hi) {
    __nv_bfloat162 t = __halves2bfloat162(lo, hi);
    return *reinterpret_cast<uint32_t*>(&t);
}

// ---------------------------------------------------------------------------
// Prep kernel 1: weight int32 -> bf16 (exact: q in 0..15), SW128 tile blocks
// ---------------------------------------------------------------------------
__global__ void wconv_kernel(const int* __restrict__ q) {
    int idx = blockIdx.x * blockDim.x + threadIdx.x;   // one thread = 8 elems
    if (idx >= NDIM * KDIM / 8) return;
    int n  = idx >> 9;
    int k0 = (idx & 511) << 3;

    const int4* p = reinterpret_cast<const int4*>(q + (size_t)n * KDIM + k0);
    int4 a = p[0], b = p[1];
    uint32_t w0 = pack_bf16f((float)a.x, (float)a.y);
    uint32_t w1 = pack_bf16f((float)a.z, (float)a.w);
    uint32_t w2 = pack_bf16f((float)b.x, (float)b.y);
    uint32_t w3 = pack_bf16f((float)b.z, (float)b.w);

    int nbp = n >> 8;
    int r   = n & 255;
    int kb  = k0 >> 6;
    int c0  = k0 & 63;
    size_t off = ((size_t)(nbp * KB + kb)) * W_TILE_BYTES
               + swz((uint32_t)(r * 128 + c0 * 2));
    *reinterpret_cast<uint4*>(g_Wb + off) = make_uint4(w0, w1, w2, w3);
}

// ---------------------------------------------------------------------------
// Prep kernel 2: x fp32 -> (hi, lo) bf16 planes (swizzled) + row sums
// ---------------------------------------------------------------------------
__global__ void xconv_kernel(const float* __restrict__ x) {
    const int m = blockIdx.x;
    const int t = threadIdx.x;    // 256 threads
    const float4* row = reinterpret_cast<const float4*>(x + (size_t)m * KDIM);
    const int mbb = m >> 7;
    const int r   = m & 127;
    const size_t abase = (size_t)mbb * ((size_t)KB * A_TILE_BYTES);

    float sum = 0.f;
    #pragma unroll
    for (int i = 0; i < 4; i++) {
        int g = t + i * 256;
        float4 v = row[g];
        sum += (v.x + v.y) + (v.z + v.w);

        __nv_bfloat16 h0 = __float2bfloat16_rn(v.x);
        __nv_bfloat16 h1 = __float2bfloat16_rn(v.y);
        __nv_bfloat16 h2 = __float2bfloat16_rn(v.z);
        __nv_bfloat16 h3 = __float2bfloat16_rn(v.w);
        __nv_bfloat16 l0 = __float2bfloat16_rn(v.x - __bfloat162float(h0));
        __nv_bfloat16 l1 = __float2bfloat16_rn(v.y - __bfloat162float(h1));
        __nv_bfloat16 l2 = __float2bfloat16_rn(v.z - __bfloat162float(h2));
        __nv_bfloat16 l3 = __float2bfloat16_rn(v.w - __bfloat162float(h3));

        int k0 = g << 2;
        int kb = k0 >> 6;
        int c0 = k0 & 63;
        size_t off = abase + (size_t)kb * A_TILE_BYTES
                   + swz((uint32_t)(r * 128 + c0 * 2));
        *reinterpret_cast<uint2*>(g_Ahi + off) =
            make_uint2(pack_bf16(h0, h1), pack_bf16(h2, h3));
        *reinterpret_cast<uint2*>(g_Alo + off) =
            make_uint2(pack_bf16(l0, l1), pack_bf16(l2, l3));
    }

    #pragma unroll
    for (int o = 16; o; o >>= 1) sum += __shfl_xor_sync(0xFFFFFFFFu, sum, o);
    __shared__ float ws[8];
    if ((t & 31) == 0) ws[t >> 5] = sum;
    __syncthreads();
    if (t == 0) {
        float s = 0.f;
        #pragma unroll
        for (int i = 0; i < 8; i++) s += ws[i];
        g_rowsum[m] = s;
    }
}

// ---------------------------------------------------------------------------
// GEMM: 128x256 CTA tile. 8 compute warps (each 32x128) + 1 producer warp.
// cp.async.bulk 3-stage pipeline; ldmatrix + mma.sync.m16n8k16 bf16;
// hi + lo A-planes accumulate into the same fp32 accumulators.
// ---------------------------------------------------------------------------
__global__ void __launch_bounds__(288, 1)
qgemm_kernel(const float* __restrict__ scale_p,
             const float* __restrict__ zp_p,
             const float* __restrict__ bias,
             float* __restrict__ out)
{
    extern __shared__ __align__(1024) unsigned char smem[];
    const uint32_t sb = smem_u32(smem);
    const int tid = threadIdx.x;
    const int wid = tid >> 5;            // 0..8
    const int lid = tid & 31;
    const int mb  = blockIdx.y;          // 0..63
    const int nbp = blockIdx.x;          // 0..15

    const uint32_t FULLB  = sb;          // 3 x 8B
    const uint32_t EMPTYB = sb + 32;     // 3 x 8B
    const uint32_t TILE0  = (sb + 2047) & ~1023u;

    if (tid == 0) {
        #pragma unroll
        for (int s = 0; s < NSTAGE; s++) {
            mbar_init(FULLB  + 8 * s, 1);   // producer expect_tx
            mbar_init(EMPTYB + 8 * s, 8);   // one arrive per compute warp
        }
        asm volatile("fence.proxy.async.shared::cta;" ::: "memory");
    }
    __syncthreads();

    // Pre-arrive: mark all stages empty (completes EMPTY phase 0).
    if (wid < 8 && lid == 0) {
        #pragma unroll
        for (int s = 0; s < NSTAGE; s++) mbar_arrive(EMPTYB + 8 * s);
    }

    if (wid == 8) {
        // ------------------------- producer -------------------------
        if (lid == 0) {
            const unsigned char* aB = g_Ahi + (size_t)mb  * ((size_t)KB * A_TILE_BYTES);
            const unsigned char* lB = g_Alo + (size_t)mb  * ((size_t)KB * A_TILE_BYTES);
            const unsigned char* wB = g_Wb  + (size_t)nbp * ((size_t)KB * W_TILE_BYTES);
            int s = 0, ph = 0;
            for (int kb = 0; kb < KB; kb++) {
                bar_wait(EMPTYB + 8 * s, ph);
                mbar_expect_tx(FULLB + 8 * s, STAGE_BYTES);
                uint32_t d = TILE0 + s * STAGE_BYTES;
                bulk_g2s(d,                    aB + (size_t)kb * A_TILE_BYTES,
                         A_TILE_BYTES, FULLB + 8 * s);
                bulk_g2s(d + A_TILE_BYTES,     lB + (size_t)kb * A_TILE_BYTES,
                         A_TILE_BYTES, FULLB + 8 * s);
                bulk_g2s(d + 2 * A_TILE_BYTES, wB + (size_t)kb * W_TILE_BYTES,
                         W_TILE_BYTES, FULLB + 8 * s);
                if (++s == NSTAGE) { s = 0; ph ^= 1; }
            }
        }
        return;
    }

    // ------------------------- compute warps -------------------------
    const int wm = wid & 3;          // M sub-tile (32 rows)
    const int wn = wid >> 2;         // N sub-tile (128 cols)
    const int g  = lid >> 3;         // ldmatrix lane group 0..3
    const int lr = lid & 7;

    // A ldmatrix address components (per m16 tile): row = mt*16 + (g&1)*8 + lr
    // byte col = ks*32 + (g>>1)*16, swizzle-XOR = (row&7)<<4
    uint32_t aRow[2], aXor[2];
    #pragma unroll
    for (int mt = 0; mt < 2; mt++) {
        int r = wm * 32 + mt * 16 + (g & 1) * 8 + lr;
        aRow[mt] = (uint32_t)(r * 128);
        aXor[mt] = (uint32_t)((r & 7) << 4);
    }
    // B (W) ldmatrix covering two n8-tiles per x4:
    // row_n = wn*128 + bt*16 + (g>>1)*8 + lr ; byte col = ks*32 + (g&1)*16
    uint32_t bRow[8], bXor[8];
    #pragma unroll
    for (int bt = 0; bt < 8; bt++) {
        int r = wn * 128 + bt * 16 + (g >> 1) * 8 + lr;
        bRow[bt] = (uint32_t)(r * 128);
        bXor[bt] = (uint32_t)((r & 7) << 4);
    }
    const uint32_t aCol = (uint32_t)((g >> 1) * 16);
    const uint32_t bCol = (uint32_t)((g & 1) * 16);

    float acc[2][16][4];
    #pragma unroll
    for (int mt = 0; mt < 2; mt++)
        #pragma unroll
        for (int nt = 0; nt < 16; nt++)
            #pragma unroll
            for (int j = 0; j < 4; j++) acc[mt][nt][j] = 0.f;

    int s = 0, ph = 0;
    for (int kb = 0; kb < KB; kb++) {
        bar_wait(FULLB + 8 * s, ph);
        const uint32_t dH = TILE0 + s * STAGE_BYTES;
        const uint32_t dL = dH + A_TILE_BYTES;
        const uint32_t dW = dH + 2 * A_TILE_BYTES;

        #pragma unroll
        for (int ks = 0; ks < 4; ks++) {
            const uint32_t kOff = (uint32_t)(ks * 32);
            // A fragments (hi and lo), 2 m16 tiles each
            uint32_t ah[2][4], al[2][4];
            #pragma unroll
            for (int mt = 0; mt < 2; mt++) {
                uint32_t off = aRow[mt] + ((kOff + aCol) ^ aXor[mt]);
                ldsm_x4(ah[mt][0], ah[mt][1], ah[mt][2], ah[mt][3], dH + off);
                ldsm_x4(al[mt][0], al[mt][1], al[mt][2], al[mt][3], dL + off);
            }
            // B fragments + MMAs, two n8-tiles per ldmatrix.x4
            #pragma unroll
            for (int bt = 0; bt < 8; bt++) {
                uint32_t b0, b1, b2, b3;
                uint32_t off = bRow[bt] + ((kOff + bCol) ^ bXor[bt]);
                ldsm_x4(b0, b1, b2, b3, dW + off);
                #pragma unroll
                for (int mt = 0; mt < 2; mt++) {
                    mma_bf16(acc[mt][2 * bt + 0], ah[mt][0], ah[mt][1], ah[mt][2], ah[mt][3], b0, b1);
                    mma_bf16(acc[mt][2 * bt + 1], ah[mt][0], ah[mt][1], ah[mt][2], ah[mt][3], b2, b3);
                    mma_bf16(acc[mt][2 * bt + 0], al[mt][0], al[mt][1], al[mt][2], al[mt][3], b0, b1);
                    mma_bf16(acc[mt][2 * bt + 1], al[mt][0], al[mt][1], al[mt][2], al[mt][3], b2, b3);
                }
            }
        }
        if (lid == 0) mbar_arrive(EMPTYB + 8 * s);
        if (++s == NSTAGE) { s = 0; ph ^= 1; }
    }

    // ------------------------- epilogue -------------------------
    const float scl = *scale_p;
    const float zp  = *zp_p;
    const int mRow0 = mb * MT + wm * 32;
    const int nCol0 = nbp * NT + wn * 128;

    #pragma unroll
    for (int mt = 0; mt < 2; mt++) {
        const int r0 = mRow0 + mt * 16 + (lid >> 2);
        const int r1 = r0 + 8;
        const float base0 = fmaf(-scl * zp, g_rowsum[r0], 0.f);
        const float base1 = fmaf(-scl * zp, g_rowsum[r1], 0.f);
        float* o0 = out + (size_t)r0 * NDIM;
        float* o1 = out + (size_t)r1 * NDIM;
        #pragma unroll
        for (int nt = 0; nt < 16; nt++) {
            const int c = nCol0 + nt * 8 + 2 * (lid & 3);
            const float2 bv = *reinterpret_cast<const float2*>(bias + c);
            float2 v0, v1;
            v0.x = fmaf(scl, acc[mt][nt][0], base0 + bv.x);
            v0.y = fmaf(scl, acc[mt][nt][1], base0 + bv.y);
            v1.x = fmaf(scl, acc[mt][nt][2], base1 + bv.x);
            v1.y = fmaf(scl, acc[mt][nt][3], base1 + bv.y);
            *reinterpret_cast<float2*>(o0 + c) = v0;
            *reinterpret_cast<float2*>(o1 + c) = v1;
        }
    }
}

// ---------------------------------------------------------------------------
// kernel_launch
// ---------------------------------------------------------------------------
extern "C" void kernel_launch(void* const* d_in, const int* in_sizes, int n_in,
                              void* d_out, int out_size)
{
    (void)in_sizes; (void)n_in; (void)out_size;
    const float* x     = (const float*)d_in[0];
    const int*   wq    = (const int*)  d_in[1];
    const float* scale = (const float*)d_in[2];
    const float* zp    = (const float*)d_in[3];
    const float* bias  = (const float*)d_in[4];
    float* out = (float*)d_out;

    wconv_kernel<<<(NDIM * KDIM / 8 + 255) / 256, 256>>>(wq);
    xconv_kernel<<<MDIM, 256>>>(x);

    cudaFuncSetAttribute(qgemm_kernel,
                         cudaFuncAttributeMaxDynamicSharedMemorySize, SMEM_TOTAL);
    dim3 grid(NDIM / NT, MDIM / MT);   // (16, 64)
    qgemm_kernel<<<grid, 288, SMEM_TOTAL>>>(scale, zp, bias, out);
}